// round 12
// baseline (speedup 1.0000x reference)
#include <cuda_runtime.h>
#include <cuda_bf16.h>
#include <math.h>

#define S_LEN 8192
#define TAGS 2048
#define RPB 14
#define NB 147                 // 146*14 + 4 = 2048 rows
#define TPB 512
#define ALPHA 8.0f
#define START_IDX 0
#define END_IDX 1

typedef unsigned long long ull;

// Tagged carried vector: each word = {low: f32 bits of value, high: epoch}.
// Published with one 8B relaxed store; the tag IS the readiness flag.
__device__ ull g_tag[2][TAGS];
__device__ float g_Mbuf[S_LEN];   // per-step global max (block 0 writes; epilogue reads)

__global__ void crf_init() {
    int i = blockIdx.x * blockDim.x + threadIdx.x;
    if (i < TAGS) {
        g_tag[0][i] = (i == START_IDX) ? (ull)0x3f800000u : 0ull;     // r_0, epoch 0
        g_tag[1][i] = 0xFFFFFFFF00000000ull;                          // sentinel epoch
    }
}

__device__ __forceinline__ __nv_bfloat162 f_as_bf2(const float& f) {
    return *reinterpret_cast<const __nv_bfloat162*>(&f);
}
__device__ __forceinline__ unsigned umax2(unsigned a, unsigned b) { return a > b ? a : b; }

__global__ void __launch_bounds__(TPB, 1) crf_main(const float* __restrict__ h,
                                                   const float* __restrict__ tr,
                                                   float* __restrict__ out) {
    __shared__ __nv_bfloat162 vbuf[2][TAGS / 2];   // parity double-buffered raw vector (bf16)
    __shared__ unsigned wmaxs[2][16];              // parity double-buffered per-warp maxes
    __shared__ double redd[TPB];                   // epilogue scratch

    const int tid = threadIdx.x;
    const int warp = tid >> 5, lane = tid & 31;
    const int b = blockIdx.x;
    const int row0 = b * RPB;
    int nrows = TAGS - row0; if (nrows > RPB) nrows = RPB;
    const bool hasrow = (warp < RPB) && (warp < nrows);

    // ---- One-time: warp r holds row (row0+r) of E = exp(transitions) in bf16.
    // Lane l owns j in { l*8 + k*256 + i : k=0..7, i=0..7 } (conflict-free LDS.128 reads).
    __nv_bfloat162 E2[32];
    if (hasrow) {
        const float* trow = tr + (size_t)(row0 + warp) * TAGS;
#pragma unroll
        for (int k = 0; k < 8; k++)
#pragma unroll
            for (int q = 0; q < 4; q++) {
                int j = lane * 8 + k * 256 + 2 * q;
                E2[k * 4 + q] = __floats2bfloat162_rn(__expf(trow[j]), __expf(trow[j + 1]));
            }
    } else {
#pragma unroll
        for (int q = 0; q < 32; q++) E2[q] = __floats2bfloat162_rn(0.f, 0.f);
    }

    float hv = (hasrow && lane == 0) ? __ldcg(h + row0 + warp) : 0.f;  // one step ahead

    for (int t = 0; t < S_LEN; t++) {
        const int par = t & 1;
        const unsigned tu = (unsigned)t;

        // off critical path: exp of current emission, prefetch next step's
        float ehv = __expf(hv);
        if (hasrow && lane == 0 && t + 1 < S_LEN)
            hv = __ldcg(h + (size_t)(t + 1) * TAGS + row0 + warp);

        // ---- gate: one lane per warp spins on one tag ----
        if (lane == 0) {
            const ull* probe = &g_tag[par][warp << 7];
            ull pq;
            for (;;) {
                asm volatile("ld.relaxed.gpu.global.b64 %0, [%1];"
                             : "=l"(pq) : "l"(probe) : "memory");
                if ((unsigned)(pq >> 32) == tu) break;
                __nanosleep(32);
            }
        }
        __syncwarp();

        // ---- verify + load own 4 tagged raw values ----
        const ull* src = &g_tag[par][4 * tid];
        ull q0, q1, q2, q3;
        do {
            asm volatile("ld.relaxed.gpu.global.b64 %0, [%1];" : "=l"(q0) : "l"(src) : "memory");
            asm volatile("ld.relaxed.gpu.global.b64 %0, [%1];" : "=l"(q1) : "l"(src + 1) : "memory");
            asm volatile("ld.relaxed.gpu.global.b64 %0, [%1];" : "=l"(q2) : "l"(src + 2) : "memory");
            asm volatile("ld.relaxed.gpu.global.b64 %0, [%1];" : "=l"(q3) : "l"(src + 3) : "memory");
        } while ((unsigned)(q0 >> 32) != tu || (unsigned)(q1 >> 32) != tu ||
                 (unsigned)(q2 >> 32) != tu || (unsigned)(q3 >> 32) != tu);

        // per-warp max (values >= 0: uint order == float order) + raw bf16 convert
        unsigned u = umax2(umax2((unsigned)q0, (unsigned)q1),
                           umax2((unsigned)q2, (unsigned)q3));
        u = __reduce_max_sync(0xffffffffu, u);
        if (lane == 0) wmaxs[par][warp] = u;
        vbuf[par][2 * tid] = __floats2bfloat162_rn(__uint_as_float((unsigned)q0),
                                                   __uint_as_float((unsigned)q1));
        vbuf[par][2 * tid + 1] = __floats2bfloat162_rn(__uint_as_float((unsigned)q2),
                                                       __uint_as_float((unsigned)q3));
        __syncthreads();   // the ONLY block barrier per step

        if (hasrow) {
            // ---- full-row dot: 8 conflict-free LDS.128, 4 bf16 chains of 8 ----
            const float4* vb4 = reinterpret_cast<const float4*>(vbuf[par]);
            float4 v = vb4[lane];
            __nv_bfloat162 a0 = __hmul2(E2[0], f_as_bf2(v.x));
            __nv_bfloat162 a1 = __hmul2(E2[1], f_as_bf2(v.y));
            __nv_bfloat162 a2 = __hmul2(E2[2], f_as_bf2(v.z));
            __nv_bfloat162 a3 = __hmul2(E2[3], f_as_bf2(v.w));
#pragma unroll
            for (int k = 1; k < 8; k++) {
                v = vb4[lane + 32 * k];
                a0 = __hfma2(E2[4 * k + 0], f_as_bf2(v.x), a0);
                a1 = __hfma2(E2[4 * k + 1], f_as_bf2(v.y), a1);
                a2 = __hfma2(E2[4 * k + 2], f_as_bf2(v.z), a2);
                a3 = __hfma2(E2[4 * k + 3], f_as_bf2(v.w), a3);
            }
            float2 g0 = __bfloat1622float2(a0), g1 = __bfloat1622float2(a1);
            float2 g2 = __bfloat1622float2(a2), g3 = __bfloat1622float2(a3);
            float rowsum = ((g0.x + g0.y) + (g1.x + g1.y)) + ((g2.x + g2.y) + (g3.x + g3.y));

            // global max of r_t (overlaps the shfl tree below)
            const uint4* W = reinterpret_cast<const uint4*>(wmaxs[par]);
            uint4 A = W[0], B = W[1], C = W[2], D = W[3];
            unsigned mm = umax2(umax2(umax2(A.x, A.y), umax2(A.z, A.w)),
                                umax2(umax2(umax2(B.x, B.y), umax2(B.z, B.w)),
                                      umax2(umax2(umax2(C.x, C.y), umax2(C.z, C.w)),
                                            umax2(umax2(D.x, D.y), umax2(D.z, D.w)))));
            float s = __fdividef(ALPHA, __uint_as_float(mm));

            // warp-wide sum of lane partials
            rowsum += __shfl_xor_sync(0xffffffffu, rowsum, 16);
            rowsum += __shfl_xor_sync(0xffffffffu, rowsum, 8);
            rowsum += __shfl_xor_sync(0xffffffffu, rowsum, 4);
            rowsum += __shfl_xor_sync(0xffffffffu, rowsum, 2);
            rowsum += __shfl_xor_sync(0xffffffffu, rowsum, 1);

            if (lane == 0) {
                float wv = ehv * s * rowsum;   // scale applied post-dot
                ull pub = ((ull)(unsigned)(t + 1) << 32) | (ull)__float_as_uint(wv);
                asm volatile("st.relaxed.gpu.global.b64 [%0], %1;"
                             :: "l"(&g_tag[(t + 1) & 1][row0 + warp]), "l"(pub) : "memory");
            }
        } else if (b == 0 && warp == 14 && lane == 0) {
            // record the global max for the epilogue
            const uint4* W = reinterpret_cast<const uint4*>(wmaxs[par]);
            uint4 A = W[0], B = W[1], C = W[2], D = W[3];
            unsigned mm = umax2(umax2(umax2(A.x, A.y), umax2(A.z, A.w)),
                                umax2(umax2(umax2(B.x, B.y), umax2(B.z, B.w)),
                                      umax2(umax2(umax2(C.x, C.y), umax2(C.z, C.w)),
                                            umax2(umax2(D.x, D.y), umax2(D.z, D.w)))));
            __stcg(&g_Mbuf[t], __uint_as_float(mm));
        }
        // next iteration's poll + double-buffered smem close the hazard window
    }

    // ---- epilogue: block 0 gathers r_S and computes log Z ----
    if (b == 0) {
        const ull* src = &g_tag[S_LEN & 1][4 * tid];
        const unsigned tu = (unsigned)S_LEN;
        ull q0, q1, q2, q3;
        do {
            asm volatile("ld.relaxed.gpu.global.b64 %0, [%1];" : "=l"(q0) : "l"(src) : "memory");
            asm volatile("ld.relaxed.gpu.global.b64 %0, [%1];" : "=l"(q1) : "l"(src + 1) : "memory");
            asm volatile("ld.relaxed.gpu.global.b64 %0, [%1];" : "=l"(q2) : "l"(src + 2) : "memory");
            asm volatile("ld.relaxed.gpu.global.b64 %0, [%1];" : "=l"(q3) : "l"(src + 3) : "memory");
        } while ((unsigned)(q0 >> 32) != tu || (unsigned)(q1 >> 32) != tu ||
                 (unsigned)(q2 >> 32) != tu || (unsigned)(q3 >> 32) != tu);

        const float* te = tr + (size_t)END_IDX * TAGS + 4 * tid;
        float dpart = __uint_as_float((unsigned)q0) * __expf(te[0])
                    + __uint_as_float((unsigned)q1) * __expf(te[1])
                    + __uint_as_float((unsigned)q2) * __expf(te[2])
                    + __uint_as_float((unsigned)q3) * __expf(te[3]);
        double lpart = 0.0;
        for (int t = tid; t < S_LEN; t += TPB)
            lpart += log((double)__ldcg(&g_Mbuf[t]));

        float* redf = reinterpret_cast<float*>(vbuf);
        redf[tid] = dpart;
        redd[tid] = lpart;
        __syncthreads();
        for (int off = TPB / 2; off > 0; off >>= 1) {
            if (tid < off) { redf[tid] += redf[tid + off]; redd[tid] += redd[tid + off]; }
            __syncthreads();
        }
        if (tid == 0)
            out[0] = (float)(redd[0] + log((double)redf[0]) -
                             (double)S_LEN * log((double)ALPHA));
    }
}

extern "C" void kernel_launch(void* const* d_in, const int* in_sizes, int n_in,
                              void* d_out, int out_size) {
    const float* a = (const float*)d_in[0];
    const float* bb = (const float*)d_in[1];
    const float* h;
    const float* tr;
    if (in_sizes[0] == S_LEN * TAGS) { h = a; tr = bb; }
    else { h = bb; tr = a; }

    crf_init<<<8, 256>>>();
    crf_main<<<NB, TPB>>>(h, tr, (float*)d_out);
}

// round 13
// speedup vs baseline: 2.5853x; 2.5853x over previous
#include <cuda_runtime.h>
#include <cuda_bf16.h>
#include <math.h>

#define S_LEN 8192
#define TAGS 2048
#define RPB 14
#define NB 147                 // 146*14 + 4 = 2048 rows
#define TPB 512
#define NWARP 16
#define JW (TAGS / NWARP)      // 128 j-columns per warp
#define JL (JW / 2)            // 64 j per lane
#define PSTRIDE 20
#define ALPHA 8.0f
#define START_IDX 0
#define END_IDX 1

typedef unsigned long long ull;

// Tagged carried vector: each word = {low: f32 bits of value, high: epoch}.
// Published with one 8B relaxed store; the tag IS the readiness flag.
__device__ ull g_tag[2][TAGS];
__device__ float g_Mbuf[S_LEN];   // per-step global max (block 0 writes; epilogue reads)

__global__ void crf_init() {
    int i = blockIdx.x * blockDim.x + threadIdx.x;
    if (i < TAGS) {
        g_tag[0][i] = (i == START_IDX) ? (ull)0x3f800000u : 0ull;   // r_0, epoch 0
        g_tag[1][i] = 0xFFFFFFFF00000000ull;                        // sentinel epoch
    }
}

__device__ __forceinline__ __nv_bfloat162 f_as_bf2(const float& f) {
    return *reinterpret_cast<const __nv_bfloat162*>(&f);
}
__device__ __forceinline__ float4 add4(float4 a, float4 b) {
    return make_float4(a.x + b.x, a.y + b.y, a.z + b.z, a.w + b.w);
}
__device__ __forceinline__ unsigned umax2(unsigned a, unsigned b) { return a > b ? a : b; }

__global__ void __launch_bounds__(TPB, 1) crf_main(const float* __restrict__ h,
                                                   const float* __restrict__ tr,
                                                   float* __restrict__ out) {
    __shared__ __nv_bfloat162 vbuf[TAGS / 2];      // 4KB raw bf16 vector (warp-private slices)
    __shared__ float P[2][2 * RPB][PSTRIDE];       // parity-buffered transposed partials
    __shared__ unsigned wmaxs[2][NWARP];           // parity-buffered per-warp maxes
    __shared__ double redd[TPB];                   // epilogue scratch

    const int tid = threadIdx.x;
    const int warp = tid >> 5, lane = tid & 31;
    const int b = blockIdx.x;
    const int row0 = b * RPB;
    int nrows = TAGS - row0; if (nrows > RPB) nrows = RPB;

    const bool act = lane < 2 * RPB;
    const int row = (lane < RPB) ? lane : lane - RPB;
    const int jh = (lane >= RPB) ? 1 : 0;

    // ---- One-time: this lane's E chunk = exp(transitions) -> 32 bf16x2 registers ----
    __nv_bfloat162 E2[32];
    if (act && row < nrows) {
        const float* trow = tr + (size_t)(row0 + row) * TAGS + warp * JW + jh * JL;
#pragma unroll
        for (int q = 0; q < 32; q++)
            E2[q] = __floats2bfloat162_rn(__expf(trow[2 * q]), __expf(trow[2 * q + 1]));
    } else {
#pragma unroll
        for (int q = 0; q < 32; q++) E2[q] = __floats2bfloat162_rn(0.f, 0.f);
    }

    const float4* v4base = reinterpret_cast<const float4*>(vbuf) + (warp * 16 + jh * 8);
    const bool comb = (warp == 0) && (lane < nrows);

    float hv = comb ? __ldcg(h + row0 + lane) : 0.f;   // one step ahead

    for (int t = 0; t < S_LEN; t++) {
        const int par = t & 1;
        const unsigned tu = (unsigned)t;

        // off critical path: exp of current emissions, prefetch next step's
        float ehv = __expf(hv);
        if (comb && t + 1 < S_LEN)
            hv = __ldcg(h + (size_t)(t + 1) * TAGS + row0 + lane);

        // ---- gate: one lane per warp spins on one tag in the warp's range ----
        if (lane == 0) {
            const ull* probe = &g_tag[par][warp << 7];
            ull pq;
            for (;;) {
                asm volatile("ld.relaxed.gpu.global.b64 %0, [%1];"
                             : "=l"(pq) : "l"(probe) : "memory");
                if ((unsigned)(pq >> 32) == tu) break;
                __nanosleep(32);
            }
        }
        __syncwarp();

        // ---- verify + load own 4 tagged raw values ----
        const ull* src = &g_tag[par][4 * tid];
        ull q0, q1, q2, q3;
        do {
            asm volatile("ld.relaxed.gpu.global.b64 %0, [%1];" : "=l"(q0) : "l"(src) : "memory");
            asm volatile("ld.relaxed.gpu.global.b64 %0, [%1];" : "=l"(q1) : "l"(src + 1) : "memory");
            asm volatile("ld.relaxed.gpu.global.b64 %0, [%1];" : "=l"(q2) : "l"(src + 2) : "memory");
            asm volatile("ld.relaxed.gpu.global.b64 %0, [%1];" : "=l"(q3) : "l"(src + 3) : "memory");
        } while ((unsigned)(q0 >> 32) != tu || (unsigned)(q1 >> 32) != tu ||
                 (unsigned)(q2 >> 32) != tu || (unsigned)(q3 >> 32) != tu);

        // ---- per-warp max (values >= 0: uint order == float order) ----
        unsigned u = umax2(umax2((unsigned)q0, (unsigned)q1),
                           umax2((unsigned)q2, (unsigned)q3));
        u = __reduce_max_sync(0xffffffffu, u);
        if (lane == 0) wmaxs[par][warp] = u;

        // ---- raw bf16 convert into warp-private vbuf slice (no scale needed) ----
        vbuf[2 * tid] = __floats2bfloat162_rn(__uint_as_float((unsigned)q0),
                                              __uint_as_float((unsigned)q1));
        vbuf[2 * tid + 1] = __floats2bfloat162_rn(__uint_as_float((unsigned)q2),
                                                  __uint_as_float((unsigned)q3));
        __syncwarp();

        // ---- 64-j dot fragment per lane: 4 chains of 8 bf16x2 ----
        float f0 = 0.f, f1 = 0.f;
#pragma unroll
        for (int c = 0; c < 4; c++) {
            float4 va = v4base[2 * c];
            float4 vb = v4base[2 * c + 1];
            __nv_bfloat162 acc = __hmul2(E2[8 * c + 0], f_as_bf2(va.x));
            acc = __hfma2(E2[8 * c + 1], f_as_bf2(va.y), acc);
            acc = __hfma2(E2[8 * c + 2], f_as_bf2(va.z), acc);
            acc = __hfma2(E2[8 * c + 3], f_as_bf2(va.w), acc);
            acc = __hfma2(E2[8 * c + 4], f_as_bf2(vb.x), acc);
            acc = __hfma2(E2[8 * c + 5], f_as_bf2(vb.y), acc);
            acc = __hfma2(E2[8 * c + 6], f_as_bf2(vb.z), acc);
            acc = __hfma2(E2[8 * c + 7], f_as_bf2(vb.w), acc);
            float2 ff = __bfloat1622float2(acc);
            f0 += ff.x; f1 += ff.y;
        }
        if (act) P[par][lane][warp] = f0 + f1;
        __syncthreads();   // the ONLY block barrier per step

        // ---- warp 0: combine, max tree, scale, coalesced publish ----
        if (warp == 0) {
            float wv = 0.f;
            // global max of r_t (cheap; off everyone else's path)
            const uint4* W = reinterpret_cast<const uint4*>(wmaxs[par]);
            uint4 A = W[0], B = W[1], C = W[2], D = W[3];
            unsigned mm = umax2(umax2(umax2(A.x, A.y), umax2(A.z, A.w)),
                                umax2(umax2(umax2(B.x, B.y), umax2(B.z, B.w)),
                                      umax2(umax2(umax2(C.x, C.y), umax2(C.z, C.w)),
                                            umax2(umax2(D.x, D.y), umax2(D.z, D.w)))));
            float s = __fdividef(ALPHA, __uint_as_float(mm));
            if (comb) {
                const float4* Pr = reinterpret_cast<const float4*>(P[par][lane]);
                const float4* Qr = reinterpret_cast<const float4*>(P[par][lane + RPB]);
                float4 s4 = add4(add4(add4(Pr[0], Pr[1]), add4(Pr[2], Pr[3])),
                                 add4(add4(Qr[0], Qr[1]), add4(Qr[2], Qr[3])));
                float sum = (s4.x + s4.y) + (s4.z + s4.w);
                wv = ehv * (s * sum);
                ull pub = ((ull)(unsigned)(t + 1) << 32) | (ull)__float_as_uint(wv);
                asm volatile("st.relaxed.gpu.global.b64 [%0], %1;"
                             :: "l"(&g_tag[(t + 1) & 1][row0 + lane]), "l"(pub) : "memory");
            }
            if (b == 0 && lane == 31) __stcg(&g_Mbuf[t], __uint_as_float(mm));
        }
        // parity double-buffering of P/wmax closes cross-iteration hazards
    }

    // ---- epilogue: block 0 gathers r_S and computes log Z ----
    if (b == 0) {
        const ull* src = &g_tag[S_LEN & 1][4 * tid];
        const unsigned tu = (unsigned)S_LEN;
        ull q0, q1, q2, q3;
        do {
            asm volatile("ld.relaxed.gpu.global.b64 %0, [%1];" : "=l"(q0) : "l"(src) : "memory");
            asm volatile("ld.relaxed.gpu.global.b64 %0, [%1];" : "=l"(q1) : "l"(src + 1) : "memory");
            asm volatile("ld.relaxed.gpu.global.b64 %0, [%1];" : "=l"(q2) : "l"(src + 2) : "memory");
            asm volatile("ld.relaxed.gpu.global.b64 %0, [%1];" : "=l"(q3) : "l"(src + 3) : "memory");
        } while ((unsigned)(q0 >> 32) != tu || (unsigned)(q1 >> 32) != tu ||
                 (unsigned)(q2 >> 32) != tu || (unsigned)(q3 >> 32) != tu);

        const float* te = tr + (size_t)END_IDX * TAGS + 4 * tid;
        float dpart = __uint_as_float((unsigned)q0) * __expf(te[0])
                    + __uint_as_float((unsigned)q1) * __expf(te[1])
                    + __uint_as_float((unsigned)q2) * __expf(te[2])
                    + __uint_as_float((unsigned)q3) * __expf(te[3]);
        double lpart = 0.0;
        for (int t = tid; t < S_LEN; t += TPB)
            lpart += log((double)__ldcg(&g_Mbuf[t]));

        float* redf = reinterpret_cast<float*>(vbuf);   // 2KB scratch
        redf[tid] = dpart;
        redd[tid] = lpart;
        __syncthreads();
        for (int off = TPB / 2; off > 0; off >>= 1) {
            if (tid < off) { redf[tid] += redf[tid + off]; redd[tid] += redd[tid + off]; }
            __syncthreads();
        }
        if (tid == 0)
            out[0] = (float)(redd[0] + log((double)redf[0]) -
                             (double)S_LEN * log((double)ALPHA));
    }
}

extern "C" void kernel_launch(void* const* d_in, const int* in_sizes, int n_in,
                              void* d_out, int out_size) {
    const float* a = (const float*)d_in[0];
    const float* bb = (const float*)d_in[1];
    const float* h;
    const float* tr;
    if (in_sizes[0] == S_LEN * TAGS) { h = a; tr = bb; }
    else { h = bb; tr = a; }

    crf_init<<<8, 256>>>();
    crf_main<<<NB, TPB>>>(h, tr, (float*)d_out);
}

// round 15
// speedup vs baseline: 2.7084x; 1.0476x over previous
#include <cuda_runtime.h>
#include <cuda_bf16.h>
#include <math.h>

#define S_LEN 8192
#define TAGS 2048
#define NWORD (TAGS / 2)       // 1024 packed words per parity
#define RPB 14
#define NB 147                 // 146*14 + 4 = 2048 rows
#define TPB 512
#define NWARP 16
#define JW (TAGS / NWARP)      // 128 j-columns per warp
#define JL (JW / 2)            // 64 j per lane
#define PSTRIDE 20
#define ALPHA 8.0f
#define START_IDX 0
#define END_IDX 1

typedef unsigned long long ull;

// Packed tagged vector: word k = {low 32: bf16x2 values (cols 2k,2k+1), high 32: epoch}.
// One 8B relaxed store publishes two values + readiness atomically.
__device__ ull g_tag[2][NWORD];
__device__ float g_Mbuf[S_LEN];   // per-step global max (block 0 writes; epilogue reads)

__global__ void crf_init() {
    int i = blockIdx.x * blockDim.x + threadIdx.x;
    if (i < NWORD) {
        // buffer 0 = r_0 (epoch 0): onehot(START_IDX=0) -> word 0 low half = bf16(1.0)
        g_tag[0][i] = (i == 0) ? (ull)0x3F80u : 0ull;
        g_tag[1][i] = 0xFFFFFFFF00000000ull;   // sentinel epoch
    }
}

__device__ __forceinline__ __nv_bfloat162 f_as_bf2(const float& f) {
    return *reinterpret_cast<const __nv_bfloat162*>(&f);
}
__device__ __forceinline__ float4 add4(float4 a, float4 b) {
    return make_float4(a.x + b.x, a.y + b.y, a.z + b.z, a.w + b.w);
}
__device__ __forceinline__ unsigned umax2(unsigned a, unsigned b) { return a > b ? a : b; }

__global__ void __launch_bounds__(TPB, 1) crf_main(const float* __restrict__ h,
                                                   const float* __restrict__ tr,
                                                   float* __restrict__ out) {
    __shared__ unsigned vbuf[TAGS / 2];            // 4KB: bf16x2 vector (warp-private slices)
    __shared__ float P[2][2 * RPB][PSTRIDE];       // parity-buffered transposed partials
    __shared__ unsigned wmaxs[2][NWARP];           // parity-buffered per-warp maxes (bf16 bits)
    __shared__ double redd[TPB];                   // epilogue scratch

    const int tid = threadIdx.x;
    const int warp = tid >> 5, lane = tid & 31;
    const int b = blockIdx.x;
    const int row0 = b * RPB;
    int nrows = TAGS - row0; if (nrows > RPB) nrows = RPB;

    const bool act = lane < 2 * RPB;
    const int row = (lane < RPB) ? lane : lane - RPB;
    const int jh = (lane >= RPB) ? 1 : 0;

    // ---- One-time: this lane's E chunk = exp(transitions) -> 32 bf16x2 registers ----
    __nv_bfloat162 E2[32];
    if (act && row < nrows) {
        const float* trow = tr + (size_t)(row0 + row) * TAGS + warp * JW + jh * JL;
#pragma unroll
        for (int q = 0; q < 32; q++)
            E2[q] = __floats2bfloat162_rn(__expf(trow[2 * q]), __expf(trow[2 * q + 1]));
    } else {
#pragma unroll
        for (int q = 0; q < 32; q++) E2[q] = __floats2bfloat162_rn(0.f, 0.f);
    }

    const float4* v4base = reinterpret_cast<const float4*>(vbuf) + (warp * 16 + jh * 8);
    const bool comb = (warp == 0) && (lane < nrows);

    float hv = comb ? __ldcg(h + row0 + lane) : 0.f;   // one step ahead

    for (int t = 0; t < S_LEN; t++) {
        const int par = t & 1;
        const unsigned tu = (unsigned)t;

        // off critical path: exp of current emissions, prefetch next step's
        float ehv = __expf(hv);
        if (comb && t + 1 < S_LEN)
            hv = __ldcg(h + (size_t)(t + 1) * TAGS + row0 + lane);

        // ---- gate: one lane per warp spins on one word in the warp's range ----
        if (lane == 0) {
            const ull* probe = &g_tag[par][warp << 6];
            ull pq;
            for (;;) {
                asm volatile("ld.relaxed.gpu.global.b64 %0, [%1];"
                             : "=l"(pq) : "l"(probe) : "memory");
                if ((unsigned)(pq >> 32) == tu) break;
                __nanosleep(32);
            }
        }
        __syncwarp();

        // ---- verify + load own 2 packed words (4 values) ----
        const ull* src = &g_tag[par][2 * tid];
        ull q0, q1;
        do {
            asm volatile("ld.relaxed.gpu.global.b64 %0, [%1];" : "=l"(q0) : "l"(src) : "memory");
            asm volatile("ld.relaxed.gpu.global.b64 %0, [%1];" : "=l"(q1) : "l"(src + 1) : "memory");
        } while ((unsigned)(q0 >> 32) != tu || (unsigned)(q1 >> 32) != tu);

        // ---- per-warp max (nonneg bf16: u16 order == value order) ----
        unsigned m2 = __vmaxu2((unsigned)q0, (unsigned)q1);
        unsigned u = umax2(m2 & 0xFFFFu, m2 >> 16);
        u = __reduce_max_sync(0xffffffffu, u);
        if (lane == 0) wmaxs[par][warp] = u;

        // ---- drop packed bf16x2 straight into warp-private vbuf slice ----
        vbuf[2 * tid] = (unsigned)q0;
        vbuf[2 * tid + 1] = (unsigned)q1;
        __syncwarp();

        // ---- 64-j dot fragment per lane: 4 chains of 8 bf16x2 ----
        float f0 = 0.f, f1 = 0.f;
#pragma unroll
        for (int c = 0; c < 4; c++) {
            float4 va = v4base[2 * c];
            float4 vb = v4base[2 * c + 1];
            __nv_bfloat162 acc = __hmul2(E2[8 * c + 0], f_as_bf2(va.x));
            acc = __hfma2(E2[8 * c + 1], f_as_bf2(va.y), acc);
            acc = __hfma2(E2[8 * c + 2], f_as_bf2(va.z), acc);
            acc = __hfma2(E2[8 * c + 3], f_as_bf2(va.w), acc);
            acc = __hfma2(E2[8 * c + 4], f_as_bf2(vb.x), acc);
            acc = __hfma2(E2[8 * c + 5], f_as_bf2(vb.y), acc);
            acc = __hfma2(E2[8 * c + 6], f_as_bf2(vb.z), acc);
            acc = __hfma2(E2[8 * c + 7], f_as_bf2(vb.w), acc);
            float2 ff = __bfloat1622float2(acc);
            f0 += ff.x; f1 += ff.y;
        }
        if (act) P[par][lane][warp] = f0 + f1;
        __syncthreads();   // the ONLY block barrier per step

        // ---- warp 0: combine, max tree, scale, packed coalesced publish ----
        if (warp == 0) {
            const uint4* W = reinterpret_cast<const uint4*>(wmaxs[par]);
            uint4 A = W[0], B = W[1], C = W[2], D = W[3];
            unsigned mm = umax2(umax2(umax2(A.x, A.y), umax2(A.z, A.w)),
                                umax2(umax2(umax2(B.x, B.y), umax2(B.z, B.w)),
                                      umax2(umax2(umax2(C.x, C.y), umax2(C.z, C.w)),
                                            umax2(umax2(D.x, D.y), umax2(D.z, D.w)))));
            float m = __bfloat162float(__ushort_as_bfloat16((unsigned short)mm));
            float s = __fdividef(ALPHA, m);
            float wv = 0.f;
            if (comb) {
                const float4* Pr = reinterpret_cast<const float4*>(P[par][lane]);
                const float4* Qr = reinterpret_cast<const float4*>(P[par][lane + RPB]);
                float4 s4 = add4(add4(add4(Pr[0], Pr[1]), add4(Pr[2], Pr[3])),
                                 add4(add4(Qr[0], Qr[1]), add4(Qr[2], Qr[3])));
                float sum = (s4.x + s4.y) + (s4.z + s4.w);
                wv = ehv * (s * sum);
            }
            // pack adjacent rows into one bf16x2 word, publish from even lanes
            unsigned my = (unsigned)__bfloat16_as_ushort(__float2bfloat16_rn(wv));
            unsigned pt = __shfl_xor_sync(0xffffffffu, my, 1);
            if (comb && !(lane & 1)) {
                unsigned packed = my | (pt << 16);
                ull pub = ((ull)(unsigned)(t + 1) << 32) | (ull)packed;
                asm volatile("st.relaxed.gpu.global.b64 [%0], %1;"
                             :: "l"(&g_tag[(t + 1) & 1][(row0 >> 1) + (lane >> 1)]),
                                "l"(pub) : "memory");
            }
            if (b == 0 && lane == 31) __stcg(&g_Mbuf[t], m);
        }
        // parity double-buffering of P/wmax closes cross-iteration hazards
    }

    // ---- epilogue: block 0 gathers r_S and computes log Z ----
    if (b == 0) {
        const ull* src = &g_tag[S_LEN & 1][2 * tid];
        const unsigned tu = (unsigned)S_LEN;
        ull q0, q1;
        do {
            asm volatile("ld.relaxed.gpu.global.b64 %0, [%1];" : "=l"(q0) : "l"(src) : "memory");
            asm volatile("ld.relaxed.gpu.global.b64 %0, [%1];" : "=l"(q1) : "l"(src + 1) : "memory");
        } while ((unsigned)(q0 >> 32) != tu || (unsigned)(q1 >> 32) != tu);

        float2 v01 = __bfloat1622float2(*reinterpret_cast<__nv_bfloat162*>(&q0));
        float2 v23 = __bfloat1622float2(*reinterpret_cast<__nv_bfloat162*>(&q1));
        const float* te = tr + (size_t)END_IDX * TAGS + 4 * tid;
        float dpart = v01.x * __expf(te[0]) + v01.y * __expf(te[1])
                    + v23.x * __expf(te[2]) + v23.y * __expf(te[3]);
        double lpart = 0.0;
        for (int t = tid; t < S_LEN; t += TPB)
            lpart += log((double)__ldcg(&g_Mbuf[t]));

        float* redf = reinterpret_cast<float*>(vbuf);   // 2KB scratch
        redf[tid] = dpart;
        redd[tid] = lpart;
        __syncthreads();
        for (int off = TPB / 2; off > 0; off >>= 1) {
            if (tid < off) { redf[tid] += redf[tid + off]; redd[tid] += redd[tid + off]; }
            __syncthreads();
        }
        if (tid == 0)
            out[0] = (float)(redd[0] + log((double)redf[0]) -
                             (double)S_LEN * log((double)ALPHA));
    }
}

extern "C" void kernel_launch(void* const* d_in, const int* in_sizes, int n_in,
                              void* d_out, int out_size) {
    const float* a = (const float*)d_in[0];
    const float* bb = (const float*)d_in[1];
    const float* h;
    const float* tr;
    if (in_sizes[0] == S_LEN * TAGS) { h = a; tr = bb; }
    else { h = bb; tr = a; }

    crf_init<<<4, 256>>>();
    crf_main<<<NB, TPB>>>(h, tr, (float*)d_out);
}